// round 1
// baseline (speedup 1.0000x reference)
#include <cuda_runtime.h>

// Fused shift + H-conv(128->8 via w1) + W-conv(8->128 via w2) on (1,128,56,56) fp32.
//
// Stage 1: inter[k4][o2][m][n] = sum_{i<64,j<3} w1[k*192+i*3+j] * X(2i+o, m+j-1, n)
//   where X(c,h,n) = x[c][(h-1+56)%56][n] if 0<=h<56 else 0   (roll(+1) then zero-pad H)
// Stage 2: out[(i32*4+k4)][m][n] = sum_{o<2,kk<3} w2[i32*6+o*3+kk] * inter[k4][o][m][n+kk-1]
//   (zero-pad W)

#define HH 56
#define WW 56
#define TM 2
#define TN 8
#define THREADS 320

__global__ __launch_bounds__(THREADS, 4)
void fused_shift_conv_kernel(const float* __restrict__ x,
                             const float* __restrict__ w1,
                             const float* __restrict__ w2,
                             float* __restrict__ out)
{
    __shared__ float w1s[768];                    // [k4][i64][j3]
    __shared__ float w2s[192];                    // [i32][o2][kk3]
    __shared__ float inter_s[4 * 2 * TM * (TN + 2)]; // [k4][o2][ml][nl]

    const int tid = threadIdx.x;
    for (int i = tid; i < 768; i += THREADS) w1s[i] = w1[i];
    for (int i = tid; i < 192; i += THREADS) w2s[i] = w2[i];
    __syncthreads();

    const int n0 = blockIdx.x * TN;   // 0..48
    const int m0 = blockIdx.y * TM;   // 0..54

    // ---------------- Phase 1: build inter tile in smem ----------------
    // 40 positions x 8-thread reduction groups.
    const int g    = tid & 7;         // i-chunk within group
    const int pos  = tid >> 3;        // 0..39
    const int nl   = pos % (TN + 2);  // 0..9 (halo columns)
    const int rest = pos / (TN + 2);  // 0..3
    const int ml   = rest & 1;
    const int o    = rest >> 1;
    const int m    = m0 + ml;
    const int ng   = n0 - 1 + nl;     // global n for this inter column

    float acc0 = 0.f, acc1 = 0.f, acc2 = 0.f, acc3 = 0.f;

    if (ng >= 0 && ng < WW) {
        int  hs[3];
        bool hv[3];
        #pragma unroll
        for (int j = 0; j < 3; ++j) {
            const int hh = m + j - 1;          // pre-roll coordinate in t
            hv[j] = (hh >= 0) && (hh < HH);
            hs[j] = (hh - 1 + HH) % HH;        // rolled source row in x
        }
        #pragma unroll
        for (int ii = 0; ii < 8; ++ii) {
            const int i = g * 8 + ii;          // i in [0,64)
            const int c = 2 * i + o;           // input channel
            const float* xb  = x + c * (HH * WW) + ng;
            const float* w1b = w1s + i * 3;
            #pragma unroll
            for (int j = 0; j < 3; ++j) {
                if (!hv[j]) continue;
                const float xv = __ldg(xb + hs[j] * WW);
                acc0 = fmaf(w1b[j],       xv, acc0);
                acc1 = fmaf(w1b[192 + j], xv, acc1);
                acc2 = fmaf(w1b[384 + j], xv, acc2);
                acc3 = fmaf(w1b[576 + j], xv, acc3);
            }
        }
    }

    // width-8 in-warp reduction (groups of 8 are warp-aligned since 8 | 32)
    #pragma unroll
    for (int off = 4; off >= 1; off >>= 1) {
        acc0 += __shfl_down_sync(0xffffffffu, acc0, off, 8);
        acc1 += __shfl_down_sync(0xffffffffu, acc1, off, 8);
        acc2 += __shfl_down_sync(0xffffffffu, acc2, off, 8);
        acc3 += __shfl_down_sync(0xffffffffu, acc3, off, 8);
    }
    if (g == 0) {
        const int b = (o * TM + ml) * (TN + 2) + nl; // k-stride = 2*TM*(TN+2) = 40
        inter_s[b]       = acc0;
        inter_s[b + 40]  = acc1;
        inter_s[b + 80]  = acc2;
        inter_s[b + 120] = acc3;
    }
    __syncthreads();

    // ---------------- Phase 2: 8 -> 128 W-conv from smem ----------------
    // 128 * TM * TN = 2048 outputs per block.
    for (int idx = tid; idx < 128 * TM * TN; idx += THREADS) {
        const int n_local = idx & (TN - 1);    // 0..7
        const int t2      = idx >> 3;
        const int ml2     = t2 & (TM - 1);     // 0..1
        const int co      = t2 >> 1;           // 0..127  (co = i32*4 + k4)
        const int i32     = co >> 2;
        const int k4      = co & 3;

        const float* w2b = w2s + i32 * 6;
        // inter idx(k4,o2,ml2,n_local+kk) = ((k4*2+o2)*TM+ml2)*(TN+2) + n_local + kk
        const float* ib  = inter_s + (k4 * 2 * TM + ml2) * (TN + 2) + n_local;

        float acc = 0.f;
        #pragma unroll
        for (int o2 = 0; o2 < 2; ++o2) {
            #pragma unroll
            for (int kk = 0; kk < 3; ++kk)
                acc = fmaf(w2b[o2 * 3 + kk], ib[o2 * TM * (TN + 2) + kk], acc);
        }
        out[co * (HH * WW) + (m0 + ml2) * WW + n0 + n_local] = acc;
    }
}

extern "C" void kernel_launch(void* const* d_in, const int* in_sizes, int n_in,
                              void* d_out, int out_size)
{
    const float* x  = (const float*)d_in[0];   // (1,128,56,56)
    const float* w1 = (const float*)d_in[1];   // (4,64,3)
    const float* w2 = (const float*)d_in[2];   // (32,2,3)
    float* out = (float*)d_out;                // (1,128,56,56)

    dim3 grid(WW / TN, HH / TM);               // (7, 28) = 196 blocks
    fused_shift_conv_kernel<<<grid, THREADS>>>(x, w1, w2, out);
}

// round 2
// speedup vs baseline: 1.9307x; 1.9307x over previous
#include <cuda_runtime.h>

// Fused shift + H-conv(128->4 per k4 via w1) + W-conv(8->128 via w2) on (1,128,56,56) fp32.
//
// Grid: (k4=4, mtile=28). Each block: 2 output rows (m0, m0+1), full width 56,
// one stage-1 k slice, all 32 stage-2 output groups for that k4.
//
// Stage 1: inter[o][m][n] = sum_{i<64,j<3} w1[k4,i,j] * X(2i+o, m+j-1, n)
//   X(c,h,n) = x[c][(h-1+56)%56][n] if 0<=h<56 else 0  (roll(+1) in H, then zero-pad H)
// Stage 2: out[i32*4+k4][m][n] = sum_{o<2,kk<3} w2[i32,o,kk] * inter[o][m][n+kk-1]  (zero-pad W)

#define HH 56
#define WW 56
#define TM 2
#define THREADS 896   // 16 s-groups x 56 n

__global__ __launch_bounds__(THREADS, 1)
void fused_shift_conv_v2(const float* __restrict__ x,
                         const float* __restrict__ w1,
                         const float* __restrict__ w2,
                         float* __restrict__ out)
{
    __shared__ float w1s[192];              // w1 slice for this k4: [i64][j3]
    __shared__ float w2s[192];              // [i32][o2][kk3]
    __shared__ float psum[16 * 56];         // [s][n] partials
    __shared__ float inter_s[2 * 2 * 58];   // [o][ml][n+1], halo cols 0 and 57 = 0

    const int tid = threadIdx.x;
    const int k4  = blockIdx.x;
    const int m0  = blockIdx.y * TM;

    for (int i = tid; i < 192; i += THREADS) {
        w1s[i] = w1[k4 * 192 + i];
        w2s[i] = w2[i];
    }
    if (tid < 8) {
        // zero n-halo of inter
        const int q = tid >> 1;
        inter_s[q * 58 + (tid & 1) * 57] = 0.f;
    }
    __syncthreads();

    // ---------------- Phase 1: partial sums, coalesced over n ----------------
    // tid = s*56 + n ; s = ig*4 + ml*2 + o
    const int n  = tid % 56;
    const int s  = tid / 56;          // 0..15
    const int o  = s & 1;
    const int ml = (s >> 1) & 1;
    const int ig = s >> 2;            // i-quarter: 16 i values
    const int m  = m0 + ml;

    // rolled+padded H source rows and validity masks for the 3 taps
    int   hoff[3];
    float msk[3];
    #pragma unroll
    for (int j = 0; j < 3; ++j) {
        const int hh = m + j - 1;                       // pre-roll coordinate
        msk[j]  = (hh >= 0 && hh < HH) ? 1.f : 0.f;
        hoff[j] = ((hh + 55) % HH) * WW;                // (hh-1+56)%56, always in range
    }

    float a0 = 0.f, a1 = 0.f, a2 = 0.f;                 // per-tap accumulators
    {
        const float* xn = x + n;
        const int ibase = ig * 16;
        #pragma unroll
        for (int ii = 0; ii < 16; ++ii) {
            const int i = ibase + ii;
            const int c = 2 * i + o;
            const float* xb = xn + c * (HH * WW);
            const float* wb = w1s + i * 3;
            a0 = fmaf(wb[0], __ldg(xb + hoff[0]), a0);
            a1 = fmaf(wb[1], __ldg(xb + hoff[1]), a1);
            a2 = fmaf(wb[2], __ldg(xb + hoff[2]), a2);
        }
    }
    float r = a0 * msk[0];
    r = fmaf(a1, msk[1], r);
    r = fmaf(a2, msk[2], r);
    psum[s * 56 + n] = r;
    __syncthreads();

    // reduce the 4 i-quarters -> inter_s
    if (tid < 4 * 56) {
        const int q  = tid / 56;      // q = ml*2 + o
        const int nn = tid % 56;
        const float sum = psum[q * 56 + nn] + psum[(4 + q) * 56 + nn]
                        + psum[(8 + q) * 56 + nn] + psum[(12 + q) * 56 + nn];
        const int oo  = q & 1;
        const int mml = q >> 1;
        inter_s[(oo * 2 + mml) * 58 + nn + 1] = sum;
    }
    __syncthreads();

    // ---------------- Phase 2: 32 output channels x 2 rows x 56 cols ----------------
    // 3584 outputs, 4 per thread, stores coalesced over n.
    #pragma unroll
    for (int idx = tid; idx < 32 * TM * 56; idx += THREADS) {
        const int n2  = idx % 56;
        const int t2  = idx / 56;
        const int ml2 = t2 & 1;
        const int i32 = t2 >> 1;

        const float* wb = w2s + i32 * 6;
        float acc = 0.f;
        #pragma unroll
        for (int o2 = 0; o2 < 2; ++o2) {
            const float* ib = inter_s + (o2 * 2 + ml2) * 58 + n2;
            #pragma unroll
            for (int kk = 0; kk < 3; ++kk)
                acc = fmaf(wb[o2 * 3 + kk], ib[kk], acc);
        }
        out[(i32 * 4 + k4) * (HH * WW) + (m0 + ml2) * WW + n2] = acc;
    }
}

extern "C" void kernel_launch(void* const* d_in, const int* in_sizes, int n_in,
                              void* d_out, int out_size)
{
    const float* x  = (const float*)d_in[0];   // (1,128,56,56)
    const float* w1 = (const float*)d_in[1];   // (4,64,3)
    const float* w2 = (const float*)d_in[2];   // (32,2,3)
    float* out = (float*)d_out;                // (1,128,56,56)

    dim3 grid(4, HH / TM);                     // (4, 28) = 112 blocks
    fused_shift_conv_v2<<<grid, THREADS>>>(x, w1, w2, out);
}